// round 1
// baseline (speedup 1.0000x reference)
#include <cuda_runtime.h>
#include <math.h>

#define HDIM 256
#define NMAX 50176
#define EMAX 800032
#define LMAX 8

// ---------------- scratch (static device globals; no allocation) ----------------
__device__ float g_h0 [(size_t)NMAX * HDIM];
__device__ float g_h1 [(size_t)NMAX * HDIM];
__device__ float g_m  [(size_t)NMAX * HDIM];
__device__ float g_agg[(size_t)NMAX * HDIM];
__device__ float g_gi [(size_t)NMAX * 3 * HDIM];
__device__ float g_gh [(size_t)NMAX * 3 * HDIM];
__device__ float g_wt [(size_t)LMAX * HDIM * HDIM];
__device__ int   g_rowptr[NMAX + 1];
__device__ int   g_fill[NMAX];
__device__ int   g_cnt [NMAX];
__device__ int   g_col [EMAX];
__device__ float g_ewS [EMAX];
__device__ int   g_is64;

// ---------------- edge-index dtype detection (int64 vs int32) -------------------
// If edge_index is int64, every odd 32-bit word (high half, values < 2^31) is 0.
__global__ void detect_k(const unsigned int* p, int E) {
    __shared__ int any;
    if (threadIdx.x == 0) any = 0;
    __syncthreads();
    int acc = 0;
    int nchk = 2048;
    for (int i = threadIdx.x; i < nchk; i += blockDim.x)
        acc |= (int)p[2 * i + 1];
    if (acc) atomicOr(&any, 1);
    __syncthreads();
    if (threadIdx.x == 0) g_is64 = (any == 0) ? 1 : 0;
}

__device__ __forceinline__ int eidx(const void* p, long long pos) {
    if (g_is64) return (int)((const long long*)p)[pos];
    return ((const int*)p)[pos];
}

// ---------------- CSR build ------------------------------------------------------
__global__ void count_k(const void* ei, int E) {
    int i = blockIdx.x * blockDim.x + threadIdx.x;
    if (i < E) atomicAdd(&g_cnt[eidx(ei, (long long)E + i)], 1);
}

__global__ void scan_k(int n) {
    __shared__ int sh[1024];
    __shared__ int carry;
    if (threadIdx.x == 0) carry = 0;
    __syncthreads();
    for (int base = 0; base < n; base += 1024) {
        int i = base + threadIdx.x;
        int v = (i < n) ? g_cnt[i] : 0;
        sh[threadIdx.x] = v;
        __syncthreads();
        #pragma unroll
        for (int off = 1; off < 1024; off <<= 1) {
            int t = (threadIdx.x >= off) ? sh[threadIdx.x - off] : 0;
            __syncthreads();
            sh[threadIdx.x] += t;
            __syncthreads();
        }
        if (i < n) {
            int ex = carry + sh[threadIdx.x] - v;   // exclusive prefix
            g_rowptr[i] = ex;
            g_fill[i]   = ex;
        }
        __syncthreads();
        if (threadIdx.x == 0) carry += sh[1023];
        __syncthreads();
    }
    if (threadIdx.x == 0) g_rowptr[n] = carry;
}

__global__ void scatter_k(const void* ei, const float* __restrict__ ew, int E) {
    int i = blockIdx.x * blockDim.x + threadIdx.x;
    if (i >= E) return;
    int d = eidx(ei, (long long)E + i);
    int s = eidx(ei, i);
    int pos = atomicAdd(&g_fill[d], 1);
    g_col[pos] = s;
    g_ewS[pos] = ew[i];
}

// ---------------- weight transpose: w[l][k][j] -> wt[l][j][k] --------------------
__global__ void transpose_k(const float* __restrict__ w, float* __restrict__ wt) {
    __shared__ float t[32][33];
    int l = blockIdx.z;
    int j0 = blockIdx.x * 32, k0 = blockIdx.y * 32;
    const float* wl  = w  + (size_t)l * HDIM * HDIM;
    float*       wtl = wt + (size_t)l * HDIM * HDIM;
    int tx = threadIdx.x, ty = threadIdx.y;
    t[ty][tx] = wl[(size_t)(k0 + ty) * HDIM + (j0 + tx)];
    __syncthreads();
    wtl[(size_t)(j0 + ty) * HDIM + (k0 + tx)] = t[tx][ty];
}

// ---------------- TN SGEMM: C[M,Nc] = A[M,K] * B[Nc,K]^T (+ bias[col]) -----------
__global__ void __launch_bounds__(256)
sgemm_tn(const float* __restrict__ A, const float* __restrict__ B,
         const float* __restrict__ bias, float* __restrict__ C,
         int M, int Nc, int K) {
    __shared__ __align__(16) float As[16][128];
    __shared__ __align__(16) float Bs[16][128];
    int tid = threadIdx.x;
    int tx = tid & 15, ty = tid >> 4;
    int bm = blockIdx.y * 128, bn = blockIdx.x * 128;

    float acc[8][8];
    #pragma unroll
    for (int i = 0; i < 8; i++)
        #pragma unroll
        for (int j = 0; j < 8; j++) acc[i][j] = 0.f;

    for (int k0 = 0; k0 < K; k0 += 16) {
        // load A tile (128 x 16), store transposed As[k][m]
        #pragma unroll
        for (int l = 0; l < 2; l++) {
            int q = tid + l * 256;
            int row = q >> 2, kc = (q & 3) << 2;
            int gr = bm + row;
            float4 v = make_float4(0.f, 0.f, 0.f, 0.f);
            if (gr < M) v = *(const float4*)(A + (size_t)gr * K + k0 + kc);
            As[kc + 0][row] = v.x; As[kc + 1][row] = v.y;
            As[kc + 2][row] = v.z; As[kc + 3][row] = v.w;
        }
        // load B tile (128 x 16), store transposed Bs[k][n]
        #pragma unroll
        for (int l = 0; l < 2; l++) {
            int q = tid + l * 256;
            int row = q >> 2, kc = (q & 3) << 2;
            int gr = bn + row;
            float4 v = make_float4(0.f, 0.f, 0.f, 0.f);
            if (gr < Nc) v = *(const float4*)(B + (size_t)gr * K + k0 + kc);
            Bs[kc + 0][row] = v.x; Bs[kc + 1][row] = v.y;
            Bs[kc + 2][row] = v.z; Bs[kc + 3][row] = v.w;
        }
        __syncthreads();

        #pragma unroll
        for (int kk = 0; kk < 16; kk++) {
            float4 a0 = *(const float4*)&As[kk][ty * 4];
            float4 a1 = *(const float4*)&As[kk][64 + ty * 4];
            float4 b0 = *(const float4*)&Bs[kk][tx * 4];
            float4 b1 = *(const float4*)&Bs[kk][64 + tx * 4];
            float a[8] = {a0.x, a0.y, a0.z, a0.w, a1.x, a1.y, a1.z, a1.w};
            float b[8] = {b0.x, b0.y, b0.z, b0.w, b1.x, b1.y, b1.z, b1.w};
            #pragma unroll
            for (int i = 0; i < 8; i++)
                #pragma unroll
                for (int j = 0; j < 8; j++)
                    acc[i][j] += a[i] * b[j];
        }
        __syncthreads();
    }

    // epilogue
    #pragma unroll
    for (int cg = 0; cg < 2; cg++) {
        int gc = bn + cg * 64 + tx * 4;
        float bv[4] = {0.f, 0.f, 0.f, 0.f};
        if (bias != nullptr && gc + 3 < Nc) {
            bv[0] = bias[gc]; bv[1] = bias[gc + 1];
            bv[2] = bias[gc + 2]; bv[3] = bias[gc + 3];
        }
        #pragma unroll
        for (int rg = 0; rg < 2; rg++) {
            #pragma unroll
            for (int i = 0; i < 4; i++) {
                int gm = bm + rg * 64 + ty * 4 + i;
                if (gm < M && gc + 3 < Nc) {
                    float4 o;
                    o.x = acc[rg * 4 + i][cg * 4 + 0] + bv[0];
                    o.y = acc[rg * 4 + i][cg * 4 + 1] + bv[1];
                    o.z = acc[rg * 4 + i][cg * 4 + 2] + bv[2];
                    o.w = acc[rg * 4 + i][cg * 4 + 3] + bv[3];
                    *(float4*)(C + (size_t)gm * Nc + gc) = o;
                }
            }
        }
    }
}

// ---------------- aggregation: agg[d] = sum_{e in CSR[d]} w_e * m[src_e] --------
__global__ void aggregate_k(const float* __restrict__ m, float* __restrict__ agg, int n) {
    int warp = (blockIdx.x * blockDim.x + threadIdx.x) >> 5;
    int lane = threadIdx.x & 31;
    if (warp >= n) return;
    int s = g_rowptr[warp], e = g_rowptr[warp + 1];
    float4 a0 = make_float4(0.f, 0.f, 0.f, 0.f);
    float4 a1 = make_float4(0.f, 0.f, 0.f, 0.f);
    for (int i = s; i < e; i++) {
        int src = g_col[i];
        float w = g_ewS[i];
        const float4* row = (const float4*)(m + (size_t)src * HDIM);
        float4 v0 = row[lane];
        float4 v1 = row[lane + 32];
        a0.x += w * v0.x; a0.y += w * v0.y; a0.z += w * v0.z; a0.w += w * v0.w;
        a1.x += w * v1.x; a1.y += w * v1.y; a1.z += w * v1.z; a1.w += w * v1.w;
    }
    float4* out = (float4*)(agg + (size_t)warp * HDIM);
    out[lane]      = a0;
    out[lane + 32] = a1;
}

// ---------------- GRU gates -----------------------------------------------------
__device__ __forceinline__ float sigf(float x) { return 1.f / (1.f + __expf(-x)); }
__device__ __forceinline__ float gru1(float gir, float giz, float gin,
                                      float ghr, float ghz, float ghn, float h) {
    float r = sigf(gir + ghr);
    float z = sigf(giz + ghz);
    float n = tanhf(gin + r * ghn);
    return (1.f - z) * n + z * h;
}

__global__ void gru_k(const float* __restrict__ gi, const float* __restrict__ gh,
                      const float* __restrict__ h, float* __restrict__ hn, int n) {
    int idx = blockIdx.x * blockDim.x + threadIdx.x;
    int total = n * (HDIM / 4);
    if (idx >= total) return;
    int row = idx / (HDIM / 4), c4 = idx % (HDIM / 4);
    const float4* gir = (const float4*)(gi + (size_t)row * 3 * HDIM) + c4;
    const float4* ghr = (const float4*)(gh + (size_t)row * 3 * HDIM) + c4;
    float4 ir = gir[0], iz = gir[HDIM / 4], in_ = gir[2 * (HDIM / 4)];
    float4 hr = ghr[0], hz = ghr[HDIM / 4], hn_ = ghr[2 * (HDIM / 4)];
    float4 hv = ((const float4*)(h + (size_t)row * HDIM))[c4];
    float4 o;
    o.x = gru1(ir.x, iz.x, in_.x, hr.x, hz.x, hn_.x, hv.x);
    o.y = gru1(ir.y, iz.y, in_.y, hr.y, hz.y, hn_.y, hv.y);
    o.z = gru1(ir.z, iz.z, in_.z, hr.z, hz.z, hn_.z, hv.z);
    o.w = gru1(ir.w, iz.w, in_.w, hr.w, hz.w, hn_.w, hv.w);
    ((float4*)(hn + (size_t)row * HDIM))[c4] = o;
}

// ---------------- final: out[n] = relu(h[n]) . fc_w + fc_b ----------------------
__global__ void final_k(const float* __restrict__ h, const float* __restrict__ fcw,
                        const float* __restrict__ fcb, float* __restrict__ out, int n) {
    int warp = (blockIdx.x * blockDim.x + threadIdx.x) >> 5;
    int lane = threadIdx.x & 31;
    if (warp >= n) return;
    const float4* hr = (const float4*)(h + (size_t)warp * HDIM);
    const float4* wr = (const float4*)fcw;
    float s = 0.f;
    #pragma unroll
    for (int l = 0; l < 2; l++) {
        float4 v = hr[lane + 32 * l];
        float4 w = wr[lane + 32 * l];
        s += fmaxf(v.x, 0.f) * w.x + fmaxf(v.y, 0.f) * w.y +
             fmaxf(v.z, 0.f) * w.z + fmaxf(v.w, 0.f) * w.w;
    }
    #pragma unroll
    for (int o = 16; o > 0; o >>= 1) s += __shfl_xor_sync(0xFFFFFFFFu, s, o);
    if (lane == 0) out[warp] = s + fcb[0];
}

// ---------------- host orchestration -------------------------------------------
extern "C" void kernel_launch(void* const* d_in, const int* in_sizes, int n_in,
                              void* d_out, int out_size) {
    const float* x    = (const float*)d_in[0];
    const void*  ei   = d_in[1];
    const float* ew   = (const float*)d_in[2];
    const float* wL   = (const float*)d_in[3];
    const float* w_ih = (const float*)d_in[4];
    const float* w_hh = (const float*)d_in[5];
    const float* b_ih = (const float*)d_in[6];
    const float* b_hh = (const float*)d_in[7];
    const float* fcw  = (const float*)d_in[8];
    const float* fcb  = (const float*)d_in[9];

    int H = in_sizes[8];            // 256
    int N = in_sizes[0] / H;        // 50000
    int E = in_sizes[2];            // 800000
    int L = in_sizes[3] / (H * H);  // 5

    float *h0, *h1, *m, *agg, *gi, *gh, *wt;
    int* cnt;
    cudaGetSymbolAddress((void**)&h0,  g_h0);
    cudaGetSymbolAddress((void**)&h1,  g_h1);
    cudaGetSymbolAddress((void**)&m,   g_m);
    cudaGetSymbolAddress((void**)&agg, g_agg);
    cudaGetSymbolAddress((void**)&gi,  g_gi);
    cudaGetSymbolAddress((void**)&gh,  g_gh);
    cudaGetSymbolAddress((void**)&wt,  g_wt);
    cudaGetSymbolAddress((void**)&cnt, g_cnt);

    cudaMemcpyAsync(h0, x, (size_t)N * H * sizeof(float), cudaMemcpyDeviceToDevice);
    cudaMemsetAsync(cnt, 0, (size_t)N * sizeof(int));

    detect_k<<<1, 256>>>((const unsigned int*)ei, E);
    {
        dim3 b(32, 32), g(H / 32, H / 32, L);
        transpose_k<<<g, b>>>(wL, wt);
    }
    count_k<<<(E + 255) / 256, 256>>>(ei, E);
    scan_k<<<1, 1024>>>(N);
    scatter_k<<<(E + 255) / 256, 256>>>(ei, ew, E);

    float* hc = h0;
    float* hx = h1;
    dim3 g1(H / 128, (N + 127) / 128);          // Nc = H
    dim3 g2((3 * H) / 128, (N + 127) / 128);    // Nc = 3H
    for (int l = 0; l < L; l++) {
        sgemm_tn<<<g1, 256>>>(hc, wt + (size_t)l * H * H, nullptr, m, N, H, H);
        aggregate_k<<<((size_t)N * 32 + 255) / 256, 256>>>(m, agg, N);
        sgemm_tn<<<g2, 256>>>(agg, w_ih, b_ih, gi, N, 3 * H, H);
        sgemm_tn<<<g2, 256>>>(hc, w_hh, b_hh, gh, N, 3 * H, H);
        gru_k<<<((size_t)N * (H / 4) + 255) / 256, 256>>>(gi, gh, hc, hx, N);
        float* t = hc; hc = hx; hx = t;
    }
    final_k<<<((size_t)N * 32 + 255) / 256, 256>>>(hc, fcw, fcb, (float*)d_out, N);
}

// round 9
// speedup vs baseline: 1.8086x; 1.8086x over previous
#include <cuda_runtime.h>
#include <cuda_bf16.h>
#include <math.h>
#include <stdint.h>

#define HDIM 256
#define NMAX 50176
#define EMAX 800032
#define LMAX 8

// ---------------- scratch (static device globals; no allocation) ----------------
__device__ float g_h0 [(size_t)NMAX * HDIM];
__device__ float g_h1 [(size_t)NMAX * HDIM];
__device__ float g_m  [(size_t)NMAX * HDIM];
__device__ float g_agg[(size_t)NMAX * HDIM];
__device__ float g_gi [(size_t)NMAX * 3 * HDIM];
__device__ float g_gh [(size_t)NMAX * 3 * HDIM];
__device__ float g_wt [(size_t)LMAX * HDIM * HDIM];
__device__ int   g_rowptr[NMAX + 1];
__device__ int   g_fill[NMAX];
__device__ int   g_cnt [NMAX];
__device__ int   g_col [EMAX];
__device__ float g_ewS [EMAX];
__device__ int   g_is64;
// bf16 split buffers: layout [rows x 512] = [hi(256) | lo(256)]
__device__ __nv_bfloat16 g_hs  [(size_t)NMAX * 512];
__device__ __nv_bfloat16 g_as  [(size_t)NMAX * 512];
__device__ __nv_bfloat16 g_wts [(size_t)LMAX * HDIM * 512];
__device__ __nv_bfloat16 g_wihs[(size_t)3 * HDIM * 512];
__device__ __nv_bfloat16 g_whhs[(size_t)3 * HDIM * 512];

// ---------------- small PTX helpers (baseline ISA only — no 'a'-gated ops) ------
__device__ __forceinline__ uint32_t s2u(const void* p) {
    uint32_t a;
    asm("{ .reg .u64 t; cvta.to.shared.u64 t, %1; cvt.u32.u64 %0, t; }" : "=r"(a) : "l"(p));
    return a;
}
__device__ __forceinline__ uint32_t sw128(uint32_t off) { return off ^ ((off >> 3) & 0x70); }
__device__ __forceinline__ void cp16(uint32_t saddr, const void* g) {
    asm volatile("cp.async.cg.shared.global [%0], [%1], 16;" :: "r"(saddr), "l"(g) : "memory");
}
__device__ __forceinline__ void cp_commit() { asm volatile("cp.async.commit_group;" ::: "memory"); }
__device__ __forceinline__ void cp_wait0()  { asm volatile("cp.async.wait_group 0;" ::: "memory"); }
__device__ __forceinline__ void ldm_x4(uint32_t* r, uint32_t addr) {
    asm volatile("ldmatrix.sync.aligned.m8n8.x4.shared.b16 {%0,%1,%2,%3}, [%4];"
                 : "=r"(r[0]), "=r"(r[1]), "=r"(r[2]), "=r"(r[3]) : "r"(addr));
}
__device__ __forceinline__ void mma16816(float* d, const uint32_t* a, uint32_t b0, uint32_t b1) {
    asm volatile(
        "mma.sync.aligned.m16n8k16.row.col.f32.bf16.bf16.f32 "
        "{%0,%1,%2,%3}, {%4,%5,%6,%7}, {%8,%9}, {%0,%1,%2,%3};"
        : "+f"(d[0]), "+f"(d[1]), "+f"(d[2]), "+f"(d[3])
        : "r"(a[0]), "r"(a[1]), "r"(a[2]), "r"(a[3]), "r"(b0), "r"(b1));
}

// ---------------- edge-index dtype detection (int64 vs int32) -------------------
__global__ void detect_k(const unsigned int* p, int E) {
    __shared__ int any;
    if (threadIdx.x == 0) any = 0;
    __syncthreads();
    int acc = 0;
    int nchk = 2048;
    for (int i = threadIdx.x; i < nchk; i += blockDim.x)
        acc |= (int)p[2 * i + 1];
    if (acc) atomicOr(&any, 1);
    __syncthreads();
    if (threadIdx.x == 0) g_is64 = (any == 0) ? 1 : 0;
}

__device__ __forceinline__ int eidx(const void* p, long long pos) {
    if (g_is64) return (int)((const long long*)p)[pos];
    return ((const int*)p)[pos];
}

// ---------------- CSR build ------------------------------------------------------
__global__ void count_k(const void* ei, int E) {
    int i = blockIdx.x * blockDim.x + threadIdx.x;
    if (i < E) atomicAdd(&g_cnt[eidx(ei, (long long)E + i)], 1);
}

__global__ void scan_k(int n) {
    __shared__ int sh[1024];
    __shared__ int carry;
    if (threadIdx.x == 0) carry = 0;
    __syncthreads();
    for (int base = 0; base < n; base += 1024) {
        int i = base + threadIdx.x;
        int v = (i < n) ? g_cnt[i] : 0;
        sh[threadIdx.x] = v;
        __syncthreads();
        #pragma unroll
        for (int off = 1; off < 1024; off <<= 1) {
            int t = (threadIdx.x >= off) ? sh[threadIdx.x - off] : 0;
            __syncthreads();
            sh[threadIdx.x] += t;
            __syncthreads();
        }
        if (i < n) {
            int ex = carry + sh[threadIdx.x] - v;
            g_rowptr[i] = ex;
            g_fill[i]   = ex;
        }
        __syncthreads();
        if (threadIdx.x == 0) carry += sh[1023];
        __syncthreads();
    }
    if (threadIdx.x == 0) g_rowptr[n] = carry;
}

__global__ void scatter_k(const void* ei, const float* __restrict__ ew, int E) {
    int i = blockIdx.x * blockDim.x + threadIdx.x;
    if (i >= E) return;
    int d = eidx(ei, (long long)E + i);
    int s = eidx(ei, i);
    int pos = atomicAdd(&g_fill[d], 1);
    g_col[pos] = s;
    g_ewS[pos] = ew[i];
}

// ---------------- weight transpose: w[l][k][j] -> wt[l][j][k] --------------------
__global__ void transpose_k(const float* __restrict__ w, float* __restrict__ wt) {
    __shared__ float t[32][33];
    int l = blockIdx.z;
    int j0 = blockIdx.x * 32, k0 = blockIdx.y * 32;
    const float* wl  = w  + (size_t)l * HDIM * HDIM;
    float*       wtl = wt + (size_t)l * HDIM * HDIM;
    int tx = threadIdx.x, ty = threadIdx.y;
    t[ty][tx] = wl[(size_t)(k0 + ty) * HDIM + (j0 + tx)];
    __syncthreads();
    wtl[(size_t)(j0 + ty) * HDIM + (k0 + tx)] = t[tx][ty];
}

// ---------------- fp32 -> bf16 (hi|lo) split: [rows x 256] -> [rows x 512] ------
__global__ void split_k(const float* __restrict__ in, __nv_bfloat16* __restrict__ out, int rows) {
    int idx = blockIdx.x * blockDim.x + threadIdx.x;
    int total = rows * 64;
    if (idx >= total) return;
    int r = idx >> 6, c4 = idx & 63;
    float4 v = ((const float4*)(in + (size_t)r * HDIM))[c4];
    __nv_bfloat16 hx = __float2bfloat16(v.x);
    __nv_bfloat16 hy = __float2bfloat16(v.y);
    __nv_bfloat16 hz = __float2bfloat16(v.z);
    __nv_bfloat16 hw = __float2bfloat16(v.w);
    __nv_bfloat16 lx = __float2bfloat16(v.x - __bfloat162float(hx));
    __nv_bfloat16 ly = __float2bfloat16(v.y - __bfloat162float(hy));
    __nv_bfloat16 lz = __float2bfloat16(v.z - __bfloat162float(hz));
    __nv_bfloat16 lw = __float2bfloat16(v.w - __bfloat162float(hw));
    __nv_bfloat162* oh = (__nv_bfloat162*)(out + (size_t)r * 512 + c4 * 4);
    __nv_bfloat162* ol = (__nv_bfloat162*)(out + (size_t)r * 512 + 256 + c4 * 4);
    oh[0] = __halves2bfloat162(hx, hy);
    oh[1] = __halves2bfloat162(hz, hw);
    ol[0] = __halves2bfloat162(lx, ly);
    ol[1] = __halves2bfloat162(lz, lw);
}

// ---------------- warp-mma (HMMA) bf16 split-K GEMM ------------------------------
// C[M, Ntot] = Afp32 * Bfp32^T + bias, via bf16 (hi,lo) split operands.
// A' : [M rows x 512] ([hi|lo]), B' : [Ntot rows x 512] ([hi|lo]).
// Logical K' = 768 as 12 panels of 64 bf16:
//   panels 0-3: A hi * B hi    4-7: A lo * B hi    8-11: A hi * B lo
// CTA tile 128x128, 8 warps (warp tile 32x64), BK=64, cp.async double buffer.
__device__ __forceinline__ int a_srcoff(int p) {
    return (p < 4) ? p * 64 : (p < 8) ? 256 + (p - 4) * 64 : (p - 8) * 64;
}
__device__ __forceinline__ int b_srcoff(int p) {
    return (p < 8) ? (p & 3) * 64 : 256 + (p - 8) * 64;
}

#define GEMM_SMEM 65536   // 2 bufs x (A 16KB + B 16KB)

__global__ void __launch_bounds__(256)
gemm_mma(const __nv_bfloat16* __restrict__ A, const __nv_bfloat16* __restrict__ B,
         const float* __restrict__ bias, float* __restrict__ C, int M, int Ntot) {
    extern __shared__ char smem[];
    uint32_t sb = s2u(smem);
    int tid = threadIdx.x, wid = tid >> 5, lane = tid & 31;
    int bm = blockIdx.x * 128, bn = blockIdx.y * 128;
    int wm = (wid & 3) * 32;        // warp m-offset within tile
    int wn = (wid >> 2) * 64;       // warp n-offset within tile

    float d[2][8][4];
    #pragma unroll
    for (int i = 0; i < 2; i++)
        #pragma unroll
        for (int j = 0; j < 8; j++)
            #pragma unroll
            for (int q = 0; q < 4; q++) d[i][j][q] = 0.f;

    // panel loader: A tile 128x64 bf16 (16KB), B tile 128x64 (16KB), SW128 rows
    int lrow = tid >> 1;
    int lseg = (tid & 1) * 64;      // byte offset within 128B row
    auto load_panel = [&](int buf, int p) {
        uint32_t ab = sb + (uint32_t)buf * 32768u;
        uint32_t bb = ab + 16384u;
        int arow = bm + lrow; if (arow >= M) arow = M - 1;
        const __nv_bfloat16* asrc = A + (size_t)arow * 512 + a_srcoff(p) + (lseg >> 1);
        const __nv_bfloat16* bsrc = B + (size_t)(bn + lrow) * 512 + b_srcoff(p) + (lseg >> 1);
        #pragma unroll
        for (int j = 0; j < 4; j++) {
            cp16(ab + sw128((uint32_t)lrow * 128 + lseg + j * 16), asrc + j * 8);
            cp16(bb + sw128((uint32_t)lrow * 128 + lseg + j * 16), bsrc + j * 8);
        }
    };

    load_panel(0, 0);
    cp_commit();

    for (int p = 0; p < 12; p++) {
        cp_wait0();
        __syncthreads();
        if (p + 1 < 12) {
            load_panel((p + 1) & 1, p + 1);
            cp_commit();
        }
        uint32_t ab = sb + (uint32_t)(p & 1) * 32768u;
        uint32_t bb = ab + 16384u;
        #pragma unroll
        for (int ks = 0; ks < 4; ks++) {
            uint32_t a[2][4];
            #pragma unroll
            for (int im = 0; im < 2; im++) {
                uint32_t r  = wm + im * 16 + (lane & 15);
                uint32_t cb = ks * 32 + ((lane >> 4) << 4);
                ldm_x4(a[im], ab + sw128(r * 128 + cb));
            }
            uint32_t b[4][4];
            #pragma unroll
            for (int ib = 0; ib < 4; ib++) {
                uint32_t r  = wn + ib * 16 + ((lane >> 4) << 3) + (lane & 7);
                uint32_t cb = ks * 32 + (((lane >> 3) & 1) << 4);
                ldm_x4(b[ib], bb + sw128(r * 128 + cb));
            }
            #pragma unroll
            for (int im = 0; im < 2; im++)
                #pragma unroll
                for (int in8 = 0; in8 < 8; in8++)
                    mma16816(d[im][in8], a[im], b[in8 >> 1][(in8 & 1) * 2],
                             b[in8 >> 1][(in8 & 1) * 2 + 1]);
        }
        __syncthreads();
    }

    // epilogue: d-frag (im,in8): rows bm+wm+im*16+(lane>>2) (+8), cols bn+wn+in8*8+(lane&3)*2
    #pragma unroll
    for (int in8 = 0; in8 < 8; in8++) {
        int col = bn + wn + in8 * 8 + (lane & 3) * 2;
        float b0 = 0.f, b1 = 0.f;
        if (bias) { b0 = bias[col]; b1 = bias[col + 1]; }
        #pragma unroll
        for (int im = 0; im < 2; im++) {
            int r0 = bm + wm + im * 16 + (lane >> 2);
            if (r0 < M) {
                float2 v = make_float2(d[im][in8][0] + b0, d[im][in8][1] + b1);
                *(float2*)(C + (size_t)r0 * Ntot + col) = v;
            }
            int r1 = r0 + 8;
            if (r1 < M) {
                float2 v = make_float2(d[im][in8][2] + b0, d[im][in8][3] + b1);
                *(float2*)(C + (size_t)r1 * Ntot + col) = v;
            }
        }
    }
}

// ---------------- aggregation: agg[d] = sum_{e in CSR[d]} w_e * m[src_e] --------
__global__ void aggregate_k(const float* __restrict__ m, float* __restrict__ agg, int n) {
    int warp = (blockIdx.x * blockDim.x + threadIdx.x) >> 5;
    int lane = threadIdx.x & 31;
    if (warp >= n) return;
    int s = g_rowptr[warp], e = g_rowptr[warp + 1];
    float4 a0 = make_float4(0.f, 0.f, 0.f, 0.f);
    float4 a1 = make_float4(0.f, 0.f, 0.f, 0.f);
    for (int i = s; i < e; i++) {
        int src = g_col[i];
        float w = g_ewS[i];
        const float4* row = (const float4*)(m + (size_t)src * HDIM);
        float4 v0 = row[lane];
        float4 v1 = row[lane + 32];
        a0.x += w * v0.x; a0.y += w * v0.y; a0.z += w * v0.z; a0.w += w * v0.w;
        a1.x += w * v1.x; a1.y += w * v1.y; a1.z += w * v1.z; a1.w += w * v1.w;
    }
    float4* out = (float4*)(agg + (size_t)warp * HDIM);
    out[lane]      = a0;
    out[lane + 32] = a1;
}

// ---------------- GRU gates -----------------------------------------------------
__device__ __forceinline__ float sigf(float x) { return 1.f / (1.f + __expf(-x)); }
__device__ __forceinline__ float gru1(float gir, float giz, float gin,
                                      float ghr, float ghz, float ghn, float h) {
    float r = sigf(gir + ghr);
    float z = sigf(giz + ghz);
    float n = tanhf(gin + r * ghn);
    return (1.f - z) * n + z * h;
}

__global__ void gru_k(const float* __restrict__ gi, const float* __restrict__ gh,
                      const float* __restrict__ h, float* __restrict__ hn, int n) {
    int idx = blockIdx.x * blockDim.x + threadIdx.x;
    int total = n * (HDIM / 4);
    if (idx >= total) return;
    int row = idx / (HDIM / 4), c4 = idx % (HDIM / 4);
    const float4* gir = (const float4*)(gi + (size_t)row * 3 * HDIM) + c4;
    const float4* ghr = (const float4*)(gh + (size_t)row * 3 * HDIM) + c4;
    float4 ir = gir[0], iz = gir[HDIM / 4], in_ = gir[2 * (HDIM / 4)];
    float4 hr = ghr[0], hz = ghr[HDIM / 4], hn_ = ghr[2 * (HDIM / 4)];
    float4 hv = ((const float4*)(h + (size_t)row * HDIM))[c4];
    float4 o;
    o.x = gru1(ir.x, iz.x, in_.x, hr.x, hz.x, hn_.x, hv.x);
    o.y = gru1(ir.y, iz.y, in_.y, hr.y, hz.y, hn_.y, hv.y);
    o.z = gru1(ir.z, iz.z, in_.z, hr.z, hz.z, hn_.z, hv.z);
    o.w = gru1(ir.w, iz.w, in_.w, hr.w, hz.w, hn_.w, hv.w);
    ((float4*)(hn + (size_t)row * HDIM))[c4] = o;
}

// ---------------- final: out[n] = relu(h[n]) . fc_w + fc_b ----------------------
__global__ void final_k(const float* __restrict__ h, const float* __restrict__ fcw,
                        const float* __restrict__ fcb, float* __restrict__ out, int n) {
    int warp = (blockIdx.x * blockDim.x + threadIdx.x) >> 5;
    int lane = threadIdx.x & 31;
    if (warp >= n) return;
    const float4* hr = (const float4*)(h + (size_t)warp * HDIM);
    const float4* wr = (const float4*)fcw;
    float s = 0.f;
    #pragma unroll
    for (int l = 0; l < 2; l++) {
        float4 v = hr[lane + 32 * l];
        float4 w = wr[lane + 32 * l];
        s += fmaxf(v.x, 0.f) * w.x + fmaxf(v.y, 0.f) * w.y +
             fmaxf(v.z, 0.f) * w.z + fmaxf(v.w, 0.f) * w.w;
    }
    #pragma unroll
    for (int o = 16; o > 0; o >>= 1) s += __shfl_xor_sync(0xFFFFFFFFu, s, o);
    if (lane == 0) out[warp] = s + fcb[0];
}

// ---------------- host orchestration -------------------------------------------
extern "C" void kernel_launch(void* const* d_in, const int* in_sizes, int n_in,
                              void* d_out, int out_size) {
    const float* x    = (const float*)d_in[0];
    const void*  ei   = d_in[1];
    const float* ew   = (const float*)d_in[2];
    const float* wL   = (const float*)d_in[3];
    const float* w_ih = (const float*)d_in[4];
    const float* w_hh = (const float*)d_in[5];
    const float* b_ih = (const float*)d_in[6];
    const float* b_hh = (const float*)d_in[7];
    const float* fcw  = (const float*)d_in[8];
    const float* fcb  = (const float*)d_in[9];

    int H = in_sizes[8];            // 256
    int N = in_sizes[0] / H;        // 50000
    int E = in_sizes[2];            // 800000
    int L = in_sizes[3] / (H * H);  // 5

    float *h0, *h1, *m, *agg, *gi, *gh, *wt;
    int* cnt;
    __nv_bfloat16 *hs, *as, *wts, *wihs, *whhs;
    cudaGetSymbolAddress((void**)&h0,   g_h0);
    cudaGetSymbolAddress((void**)&h1,   g_h1);
    cudaGetSymbolAddress((void**)&m,    g_m);
    cudaGetSymbolAddress((void**)&agg,  g_agg);
    cudaGetSymbolAddress((void**)&gi,   g_gi);
    cudaGetSymbolAddress((void**)&gh,   g_gh);
    cudaGetSymbolAddress((void**)&wt,   g_wt);
    cudaGetSymbolAddress((void**)&cnt,  g_cnt);
    cudaGetSymbolAddress((void**)&hs,   g_hs);
    cudaGetSymbolAddress((void**)&as,   g_as);
    cudaGetSymbolAddress((void**)&wts,  g_wts);
    cudaGetSymbolAddress((void**)&wihs, g_wihs);
    cudaGetSymbolAddress((void**)&whhs, g_whhs);

    cudaFuncSetAttribute(gemm_mma, cudaFuncAttributeMaxDynamicSharedMemorySize, GEMM_SMEM);

    cudaMemcpyAsync(h0, x, (size_t)N * H * sizeof(float), cudaMemcpyDeviceToDevice);
    cudaMemsetAsync(cnt, 0, (size_t)N * sizeof(int));

    detect_k<<<1, 256>>>((const unsigned int*)ei, E);
    {
        dim3 b(32, 32), g(H / 32, H / 32, L);
        transpose_k<<<g, b>>>(wL, wt);
    }
    count_k<<<(E + 255) / 256, 256>>>(ei, E);
    scan_k<<<1, 1024>>>(N);
    scatter_k<<<(E + 255) / 256, 256>>>(ei, ew, E);

    // weight splits (fp32 -> bf16 hi|lo)
    split_k<<<((size_t)L * H * 64 + 255) / 256, 256>>>(wt, wts, L * H);
    split_k<<<((size_t)3 * H * 64 + 255) / 256, 256>>>(w_ih, wihs, 3 * H);
    split_k<<<((size_t)3 * H * 64 + 255) / 256, 256>>>(w_hh, whhs, 3 * H);

    float* hc = h0;
    float* hx = h1;
    int mtiles = (N + 127) / 128;
    dim3 gm_(mtiles, 2);     // Ntot = 256 -> 2 n-tiles
    dim3 gg_(mtiles, 6);     // Ntot = 768 -> 6 n-tiles
    int splitgrid = ((size_t)N * 64 + 255) / 256;

    for (int l = 0; l < L; l++) {
        split_k<<<splitgrid, 256>>>(hc, hs, N);
        gemm_mma<<<gm_, 256, GEMM_SMEM>>>(hs, wts + (size_t)l * H * 512, nullptr, m, N, H);
        aggregate_k<<<((size_t)N * 32 + 255) / 256, 256>>>(m, agg, N);
        split_k<<<splitgrid, 256>>>(agg, as, N);
        gemm_mma<<<gg_, 256, GEMM_SMEM>>>(as, wihs, b_ih, gi, N, 3 * H);
        gemm_mma<<<gg_, 256, GEMM_SMEM>>>(hs, whhs, b_hh, gh, N, 3 * H);
        gru_k<<<((size_t)N * (H / 4) + 255) / 256, 256>>>(gi, gh, hc, hx, N);
        float* t = hc; hc = hx; hx = t;
    }
    final_k<<<((size_t)N * 32 + 255) / 256, 256>>>(hc, fcw, fcb, (float*)d_out, N);
}

// round 11
// speedup vs baseline: 1.9413x; 1.0734x over previous
#include <cuda_runtime.h>
#include <cuda_bf16.h>
#include <math.h>
#include <stdint.h>

#define HDIM 256
#define NMAX 50176
#define EMAX 800032
#define LMAX 8

// ---------------- scratch (static device globals; no allocation) ----------------
__device__ float g_h0 [(size_t)NMAX * HDIM];
__device__ float g_h1 [(size_t)NMAX * HDIM];
__device__ float g_m  [(size_t)NMAX * HDIM];
__device__ float g_gi [(size_t)NMAX * 3 * HDIM];
__device__ float g_gh [(size_t)NMAX * 3 * HDIM];
__device__ float g_wt [(size_t)LMAX * HDIM * HDIM];
__device__ int   g_rowptr[NMAX + 1];
__device__ int   g_fill[NMAX];
__device__ int   g_cnt [NMAX];
__device__ int   g_bsum[256];
__device__ int   g_boff[256];
__device__ int   g_col [EMAX];
__device__ float g_ewS [EMAX];
__device__ int   g_is64;
// bf16 split buffers: layout [rows x 512] = [hi(256) | lo(256)]
__device__ __nv_bfloat16 g_hs [(size_t)NMAX * 512];
__device__ __nv_bfloat16 g_as [(size_t)NMAX * 512];
__device__ __nv_bfloat16 g_wts[(size_t)LMAX * HDIM * 512];
__device__ __nv_bfloat16 g_wgs[(size_t)2 * 3 * HDIM * 512];   // [w_ih | w_hh] splits

// ---------------- small PTX helpers (baseline ISA only) -------------------------
__device__ __forceinline__ uint32_t s2u(const void* p) {
    uint32_t a;
    asm("{ .reg .u64 t; cvta.to.shared.u64 t, %1; cvt.u32.u64 %0, t; }" : "=r"(a) : "l"(p));
    return a;
}
__device__ __forceinline__ uint32_t sw128(uint32_t off) { return off ^ ((off >> 3) & 0x70); }
__device__ __forceinline__ void cp16(uint32_t saddr, const void* g) {
    asm volatile("cp.async.cg.shared.global [%0], [%1], 16;" :: "r"(saddr), "l"(g) : "memory");
}
__device__ __forceinline__ void cp_commit() { asm volatile("cp.async.commit_group;" ::: "memory"); }
__device__ __forceinline__ void cp_wait0()  { asm volatile("cp.async.wait_group 0;" ::: "memory"); }
__device__ __forceinline__ void cp_wait1()  { asm volatile("cp.async.wait_group 1;" ::: "memory"); }
__device__ __forceinline__ void ldm_x4(uint32_t* r, uint32_t addr) {
    asm volatile("ldmatrix.sync.aligned.m8n8.x4.shared.b16 {%0,%1,%2,%3}, [%4];"
                 : "=r"(r[0]), "=r"(r[1]), "=r"(r[2]), "=r"(r[3]) : "r"(addr));
}
__device__ __forceinline__ void mma16816(float* d, const uint32_t* a, uint32_t b0, uint32_t b1) {
    asm volatile(
        "mma.sync.aligned.m16n8k16.row.col.f32.bf16.bf16.f32 "
        "{%0,%1,%2,%3}, {%4,%5,%6,%7}, {%8,%9}, {%0,%1,%2,%3};"
        : "+f"(d[0]), "+f"(d[1]), "+f"(d[2]), "+f"(d[3])
        : "r"(a[0]), "r"(a[1]), "r"(a[2]), "r"(a[3]), "r"(b0), "r"(b1));
}

// ---------------- edge-index dtype detection (int64 vs int32) -------------------
__global__ void detect_k(const unsigned int* p, int E) {
    __shared__ int any;
    if (threadIdx.x == 0) any = 0;
    __syncthreads();
    int acc = 0;
    int nchk = 2048;
    for (int i = threadIdx.x; i < nchk; i += blockDim.x)
        acc |= (int)p[2 * i + 1];
    if (acc) atomicOr(&any, 1);
    __syncthreads();
    if (threadIdx.x == 0) g_is64 = (any == 0) ? 1 : 0;
}

__device__ __forceinline__ int eidx(const void* p, long long pos) {
    if (g_is64) return (int)((const long long*)p)[pos];
    return ((const int*)p)[pos];
}

// ---------------- CSR build ------------------------------------------------------
__global__ void count_k(const void* ei, int E) {
    int i = blockIdx.x * blockDim.x + threadIdx.x;
    if (i < E) atomicAdd(&g_cnt[eidx(ei, (long long)E + i)], 1);
}

// 3-phase parallel exclusive scan over g_cnt -> g_rowptr / g_fill
__global__ void scanA_k(int n) {
    __shared__ int sh[256];
    int t = threadIdx.x;
    int i = blockIdx.x * 256 + t;
    int v = (i < n) ? g_cnt[i] : 0;
    sh[t] = v;
    __syncthreads();
    #pragma unroll
    for (int off = 1; off < 256; off <<= 1) {
        int tv = (t >= off) ? sh[t - off] : 0;
        __syncthreads();
        sh[t] += tv;
        __syncthreads();
    }
    if (i < n) g_rowptr[i] = sh[t] - v;       // local exclusive
    if (t == 255) g_bsum[blockIdx.x] = sh[255];
}
__global__ void scanB_k(int nb) {
    __shared__ int sh[256];
    int t = threadIdx.x;
    int v = (t < nb) ? g_bsum[t] : 0;
    sh[t] = v;
    __syncthreads();
    #pragma unroll
    for (int off = 1; off < 256; off <<= 1) {
        int tv = (t >= off) ? sh[t - off] : 0;
        __syncthreads();
        sh[t] += tv;
        __syncthreads();
    }
    g_boff[t] = sh[t] - v;                    // exclusive block offset
}
__global__ void scanC_k(int n, int E) {
    int i = blockIdx.x * 256 + threadIdx.x;
    if (i < n) {
        int r = g_rowptr[i] + g_boff[blockIdx.x];
        g_rowptr[i] = r;
        g_fill[i]   = r;
    }
    if (i == 0) g_rowptr[n] = E;
}

__global__ void scatter_k(const void* ei, const float* __restrict__ ew, int E) {
    int i = blockIdx.x * blockDim.x + threadIdx.x;
    if (i >= E) return;
    int d = eidx(ei, (long long)E + i);
    int s = eidx(ei, i);
    int pos = atomicAdd(&g_fill[d], 1);
    g_col[pos] = s;
    g_ewS[pos] = ew[i];
}

// ---------------- weight transpose: w[l][k][j] -> wt[l][j][k] --------------------
__global__ void transpose_k(const float* __restrict__ w, float* __restrict__ wt) {
    __shared__ float t[32][33];
    int l = blockIdx.z;
    int j0 = blockIdx.x * 32, k0 = blockIdx.y * 32;
    const float* wl  = w  + (size_t)l * HDIM * HDIM;
    float*       wtl = wt + (size_t)l * HDIM * HDIM;
    int tx = threadIdx.x, ty = threadIdx.y;
    t[ty][tx] = wl[(size_t)(k0 + ty) * HDIM + (j0 + tx)];
    __syncthreads();
    wtl[(size_t)(j0 + ty) * HDIM + (k0 + tx)] = t[tx][ty];
}

// ---------------- fp32 -> bf16 (hi|lo) split: [rows x 256] -> [rows x 512] ------
__device__ __forceinline__ void split4(float4 v, __nv_bfloat162* oh, __nv_bfloat162* ol) {
    __nv_bfloat16 hx = __float2bfloat16(v.x);
    __nv_bfloat16 hy = __float2bfloat16(v.y);
    __nv_bfloat16 hz = __float2bfloat16(v.z);
    __nv_bfloat16 hw = __float2bfloat16(v.w);
    oh[0] = __halves2bfloat162(hx, hy);
    oh[1] = __halves2bfloat162(hz, hw);
    ol[0] = __halves2bfloat162(__float2bfloat16(v.x - __bfloat162float(hx)),
                               __float2bfloat16(v.y - __bfloat162float(hy)));
    ol[1] = __halves2bfloat162(__float2bfloat16(v.z - __bfloat162float(hz)),
                               __float2bfloat16(v.w - __bfloat162float(hw)));
}

__global__ void split_k(const float* __restrict__ in, __nv_bfloat16* __restrict__ out, int rows) {
    int idx = blockIdx.x * blockDim.x + threadIdx.x;
    int total = rows * 64;
    if (idx >= total) return;
    int r = idx >> 6, c4 = idx & 63;
    float4 v = ((const float4*)(in + (size_t)r * HDIM))[c4];
    split4(v, (__nv_bfloat162*)(out + (size_t)r * 512 + c4 * 4),
              (__nv_bfloat162*)(out + (size_t)r * 512 + 256 + c4 * 4));
}

// ---------------- warp-mma (HMMA) bf16 split-K GEMM, 3-stage pipeline ------------
// C[M, Ntot] = Afp32 * Bfp32^T + bias, via bf16 (hi,lo) split operands.
// 12 K-panels of 64: 0-3 Ahi*Bhi, 4-7 Alo*Bhi, 8-11 Ahi*Blo.
// CTA tile 128x128, 8 warps (32x64 each), 3-stage cp.async ring (96KB smem).
// blockIdx.z selects (A, bias, C); B offset = z * bstride.
__device__ __forceinline__ int a_srcoff(int p) {
    return (p < 4) ? p * 64 : (p < 8) ? 256 + (p - 4) * 64 : (p - 8) * 64;
}
__device__ __forceinline__ int b_srcoff(int p) {
    return (p < 8) ? (p & 3) * 64 : 256 + (p - 8) * 64;
}

#define GEMM_SMEM 98304   // 3 stages x (A 16KB + B 16KB)

__global__ void __launch_bounds__(256, 2)
gemm_mma(const __nv_bfloat16* __restrict__ A0, const __nv_bfloat16* __restrict__ A1,
         const __nv_bfloat16* __restrict__ Bw, size_t bstride,
         const float* __restrict__ bias0, const float* __restrict__ bias1,
         float* __restrict__ C0, float* __restrict__ C1, int M, int Ntot) {
    extern __shared__ char smem[];
    uint32_t sb = s2u(smem);
    int tid = threadIdx.x, wid = tid >> 5, lane = tid & 31;
    int bm = blockIdx.x * 128, bn = blockIdx.y * 128;
    const __nv_bfloat16* A = blockIdx.z ? A1 : A0;
    const __nv_bfloat16* B = Bw + (size_t)blockIdx.z * bstride;
    const float* bias = blockIdx.z ? bias1 : bias0;
    float* C = blockIdx.z ? C1 : C0;
    int wm = (wid & 3) * 32;
    int wn = (wid >> 2) * 64;

    float d[2][8][4];
    #pragma unroll
    for (int i = 0; i < 2; i++)
        #pragma unroll
        for (int j = 0; j < 8; j++)
            #pragma unroll
            for (int q = 0; q < 4; q++) d[i][j][q] = 0.f;

    int lrow = tid >> 1;
    int lseg = (tid & 1) * 64;
    auto load_panel = [&](int buf, int p) {
        uint32_t ab = sb + (uint32_t)buf * 32768u;
        uint32_t bb = ab + 16384u;
        int arow = bm + lrow; if (arow >= M) arow = M - 1;
        const __nv_bfloat16* asrc = A + (size_t)arow * 512 + a_srcoff(p) + (lseg >> 1);
        const __nv_bfloat16* bsrc = B + (size_t)(bn + lrow) * 512 + b_srcoff(p) + (lseg >> 1);
        #pragma unroll
        for (int j = 0; j < 4; j++) {
            cp16(ab + sw128((uint32_t)lrow * 128 + lseg + j * 16), asrc + j * 8);
            cp16(bb + sw128((uint32_t)lrow * 128 + lseg + j * 16), bsrc + j * 8);
        }
    };

    load_panel(0, 0); cp_commit();
    load_panel(1, 1); cp_commit();

    for (int p = 0; p < 12; p++) {
        if (p == 11) cp_wait0(); else cp_wait1();
        __syncthreads();
        if (p + 2 < 12) {
            load_panel((p + 2) % 3, p + 2);
            cp_commit();
        }
        uint32_t ab = sb + (uint32_t)(p % 3) * 32768u;
        uint32_t bb = ab + 16384u;
        #pragma unroll
        for (int ks = 0; ks < 4; ks++) {
            uint32_t a[2][4];
            #pragma unroll
            for (int im = 0; im < 2; im++) {
                uint32_t r  = wm + im * 16 + (lane & 15);
                uint32_t cb = ks * 32 + ((lane >> 4) << 4);
                ldm_x4(a[im], ab + sw128(r * 128 + cb));
            }
            uint32_t b[4][4];
            #pragma unroll
            for (int ib = 0; ib < 4; ib++) {
                uint32_t r  = wn + ib * 16 + ((lane >> 4) << 3) + (lane & 7);
                uint32_t cb = ks * 32 + (((lane >> 3) & 1) << 4);
                ldm_x4(b[ib], bb + sw128(r * 128 + cb));
            }
            #pragma unroll
            for (int im = 0; im < 2; im++)
                #pragma unroll
                for (int in8 = 0; in8 < 8; in8++)
                    mma16816(d[im][in8], a[im], b[in8 >> 1][(in8 & 1) * 2],
                             b[in8 >> 1][(in8 & 1) * 2 + 1]);
        }
        __syncthreads();
    }

    #pragma unroll
    for (int in8 = 0; in8 < 8; in8++) {
        int col = bn + wn + in8 * 8 + (lane & 3) * 2;
        float b0 = 0.f, b1 = 0.f;
        if (bias) { b0 = bias[col]; b1 = bias[col + 1]; }
        #pragma unroll
        for (int im = 0; im < 2; im++) {
            int r0 = bm + wm + im * 16 + (lane >> 2);
            if (r0 < M) {
                float2 v = make_float2(d[im][in8][0] + b0, d[im][in8][1] + b1);
                *(float2*)(C + (size_t)r0 * Ntot + col) = v;
            }
            int r1 = r0 + 8;
            if (r1 < M) {
                float2 v = make_float2(d[im][in8][2] + b0, d[im][in8][3] + b1);
                *(float2*)(C + (size_t)r1 * Ntot + col) = v;
            }
        }
    }
}

// -------- aggregation: as[d] = split( sum_{e in CSR[d]} w_e * m[src_e] ) --------
__global__ void aggregate_k(const float* __restrict__ m, __nv_bfloat16* __restrict__ as, int n) {
    int warp = (blockIdx.x * blockDim.x + threadIdx.x) >> 5;
    int lane = threadIdx.x & 31;
    if (warp >= n) return;
    int s = g_rowptr[warp], e = g_rowptr[warp + 1];
    float4 a0 = make_float4(0.f, 0.f, 0.f, 0.f);
    float4 a1 = make_float4(0.f, 0.f, 0.f, 0.f);
    for (int i = s; i < e; i++) {
        int src = g_col[i];
        float w = g_ewS[i];
        const float4* row = (const float4*)(m + (size_t)src * HDIM);
        float4 v0 = row[lane];
        float4 v1 = row[lane + 32];
        a0.x += w * v0.x; a0.y += w * v0.y; a0.z += w * v0.z; a0.w += w * v0.w;
        a1.x += w * v1.x; a1.y += w * v1.y; a1.z += w * v1.z; a1.w += w * v1.w;
    }
    __nv_bfloat16* row = as + (size_t)warp * 512;
    split4(a0, (__nv_bfloat162*)(row + lane * 4),       (__nv_bfloat162*)(row + 256 + lane * 4));
    split4(a1, (__nv_bfloat162*)(row + 128 + lane * 4), (__nv_bfloat162*)(row + 384 + lane * 4));
}

// ---------------- GRU gates (fused split output for next layer) -----------------
__device__ __forceinline__ float sigf(float x) { return 1.f / (1.f + __expf(-x)); }
__device__ __forceinline__ float gru1(float gir, float giz, float gin,
                                      float ghr, float ghz, float ghn, float h) {
    float r = sigf(gir + ghr);
    float z = sigf(giz + ghz);
    float n = tanhf(gin + r * ghn);
    return (1.f - z) * n + z * h;
}

__global__ void gru_k(const float* __restrict__ gi, const float* __restrict__ gh,
                      const float* __restrict__ h, float* __restrict__ hn,
                      __nv_bfloat16* __restrict__ hs, int n) {
    int idx = blockIdx.x * blockDim.x + threadIdx.x;
    int total = n * (HDIM / 4);
    if (idx >= total) return;
    int row = idx / (HDIM / 4), c4 = idx % (HDIM / 4);
    const float4* gir = (const float4*)(gi + (size_t)row * 3 * HDIM) + c4;
    const float4* ghr = (const float4*)(gh + (size_t)row * 3 * HDIM) + c4;
    float4 ir = gir[0], iz = gir[HDIM / 4], in_ = gir[2 * (HDIM / 4)];
    float4 hr = ghr[0], hz = ghr[HDIM / 4], hn_ = ghr[2 * (HDIM / 4)];
    float4 hv = ((const float4*)(h + (size_t)row * HDIM))[c4];
    float4 o;
    o.x = gru1(ir.x, iz.x, in_.x, hr.x, hz.x, hn_.x, hv.x);
    o.y = gru1(ir.y, iz.y, in_.y, hr.y, hz.y, hn_.y, hv.y);
    o.z = gru1(ir.z, iz.z, in_.z, hr.z, hz.z, hn_.z, hv.z);
    o.w = gru1(ir.w, iz.w, in_.w, hr.w, hz.w, hn_.w, hv.w);
    ((float4*)(hn + (size_t)row * HDIM))[c4] = o;
    __nv_bfloat16* srow = hs + (size_t)row * 512;
    split4(o, (__nv_bfloat162*)(srow + c4 * 4), (__nv_bfloat162*)(srow + 256 + c4 * 4));
}

// ---------------- final: out[n] = relu(h[n]) . fc_w + fc_b ----------------------
__global__ void final_k(const float* __restrict__ h, const float* __restrict__ fcw,
                        const float* __restrict__ fcb, float* __restrict__ out, int n) {
    int warp = (blockIdx.x * blockDim.x + threadIdx.x) >> 5;
    int lane = threadIdx.x & 31;
    if (warp >= n) return;
    const float4* hr = (const float4*)(h + (size_t)warp * HDIM);
    const float4* wr = (const float4*)fcw;
    float s = 0.f;
    #pragma unroll
    for (int l = 0; l < 2; l++) {
        float4 v = hr[lane + 32 * l];
        float4 w = wr[lane + 32 * l];
        s += fmaxf(v.x, 0.f) * w.x + fmaxf(v.y, 0.f) * w.y +
             fmaxf(v.z, 0.f) * w.z + fmaxf(v.w, 0.f) * w.w;
    }
    #pragma unroll
    for (int o = 16; o > 0; o >>= 1) s += __shfl_xor_sync(0xFFFFFFFFu, s, o);
    if (lane == 0) out[warp] = s + fcb[0];
}

// ---------------- host orchestration -------------------------------------------
extern "C" void kernel_launch(void* const* d_in, const int* in_sizes, int n_in,
                              void* d_out, int out_size) {
    const float* x    = (const float*)d_in[0];
    const void*  ei   = d_in[1];
    const float* ew   = (const float*)d_in[2];
    const float* wL   = (const float*)d_in[3];
    const float* w_ih = (const float*)d_in[4];
    const float* w_hh = (const float*)d_in[5];
    const float* b_ih = (const float*)d_in[6];
    const float* b_hh = (const float*)d_in[7];
    const float* fcw  = (const float*)d_in[8];
    const float* fcb  = (const float*)d_in[9];

    int H = in_sizes[8];            // 256
    int N = in_sizes[0] / H;        // 50000
    int E = in_sizes[2];            // 800000
    int L = in_sizes[3] / (H * H);  // 5

    float *h0, *h1, *m, *gi, *gh, *wt;
    int* cnt;
    __nv_bfloat16 *hs, *as, *wts, *wgs;
    cudaGetSymbolAddress((void**)&h0,  g_h0);
    cudaGetSymbolAddress((void**)&h1,  g_h1);
    cudaGetSymbolAddress((void**)&m,   g_m);
    cudaGetSymbolAddress((void**)&gi,  g_gi);
    cudaGetSymbolAddress((void**)&gh,  g_gh);
    cudaGetSymbolAddress((void**)&wt,  g_wt);
    cudaGetSymbolAddress((void**)&cnt, g_cnt);
    cudaGetSymbolAddress((void**)&hs,  g_hs);
    cudaGetSymbolAddress((void**)&as,  g_as);
    cudaGetSymbolAddress((void**)&wts, g_wts);
    cudaGetSymbolAddress((void**)&wgs, g_wgs);

    cudaFuncSetAttribute(gemm_mma, cudaFuncAttributeMaxDynamicSharedMemorySize, GEMM_SMEM);

    cudaMemcpyAsync(h0, x, (size_t)N * H * sizeof(float), cudaMemcpyDeviceToDevice);
    cudaMemsetAsync(cnt, 0, (size_t)N * sizeof(int));

    int nb = (N + 255) / 256;
    detect_k<<<1, 256>>>((const unsigned int*)ei, E);
    {
        dim3 b(32, 32), g(H / 32, H / 32, L);
        transpose_k<<<g, b>>>(wL, wt);
    }
    count_k<<<(E + 255) / 256, 256>>>(ei, E);
    scanA_k<<<nb, 256>>>(N);
    scanB_k<<<1, 256>>>(nb);
    scanC_k<<<nb, 256>>>(N, E);
    scatter_k<<<(E + 255) / 256, 256>>>(ei, ew, E);

    // weight splits (fp32 -> bf16 hi|lo)
    split_k<<<((size_t)L * H * 64 + 255) / 256, 256>>>(wt, wts, L * H);
    split_k<<<((size_t)3 * H * 64 + 255) / 256, 256>>>(w_ih, wgs, 3 * H);
    split_k<<<((size_t)3 * H * 64 + 255) / 256, 256>>>(w_hh, wgs + (size_t)3 * H * 512, 3 * H);
    // initial h split (layer 0 input)
    split_k<<<((size_t)N * 64 + 255) / 256, 256>>>(h0, hs, N);

    float* hc = h0;
    float* hx = h1;
    int mtiles = (N + 127) / 128;
    dim3 gm_(mtiles, 2, 1);     // Ntot = 256
    dim3 gg_(mtiles, 6, 2);     // Ntot = 768, z: 0=gi, 1=gh

    for (int l = 0; l < L; l++) {
        gemm_mma<<<gm_, 256, GEMM_SMEM>>>(hs, hs, wts + (size_t)l * H * 512, 0,
                                          nullptr, nullptr, m, m, N, H);
        aggregate_k<<<((size_t)N * 32 + 255) / 256, 256>>>(m, as, N);
        gemm_mma<<<gg_, 256, GEMM_SMEM>>>(as, hs, wgs, (size_t)3 * H * 512,
                                          b_ih, b_hh, gi, gh, N, 3 * H);
        gru_k<<<((size_t)N * (H / 4) + 255) / 256, 256>>>(gi, gh, hc, hx, hs, N);
        float* t = hc; hc = hx; hx = t;
    }
    final_k<<<((size_t)N * 32 + 255) / 256, 256>>>(hc, fcw, fcb, (float*)d_out, N);
}